// round 7
// baseline (speedup 1.0000x reference)
#include <cuda_runtime.h>

#define BB 2
#define DD 64
#define HH 128
#define WW 128
#define NS (BB*DD)      // 128 slices
#define NBLK NS         // one block per slice
#define NT 512
#define NWARP 16
#define GR 10           // guard rows each side (zero-filled)
#define SROWS (HH + 2*GR)
#define SSTR 6          // words per stored row: [guardW-1, W0..W3, guardW4]

struct Ent { signed char dr, dc; short gc; float sv; };  // 8B, gc = d2 at group close

constexpr int count_tab() {
    int n = 0;
    for (int dr = -9; dr <= 9; ++dr)
        for (int dc = -9; dc <= 9; ++dc) {
            int d2 = dr * dr + dc * dc;
            if (d2 >= 1 && d2 <= 99) ++n;
        }
    return n;
}
constexpr int TABN = count_tab();
static_assert(TABN == 304, "offset table size");

constexpr double csqrt_(double x) {
    double g = x > 1.0 ? x : 1.0;
    for (int i = 0; i < 60; ++i) g = 0.5 * (g + x / g);
    return g;
}
struct Tab { Ent e[TABN]; };
constexpr Tab make_tab() {
    Tab t{};
    int n = 0;
    for (int d2 = 1; d2 <= 99; ++d2) {          // ascending-d2 group order
        int start = n;
        for (int dr = -9; dr <= 9; ++dr)
            for (int dc = -9; dc <= 9; ++dc)
                if (dr * dr + dc * dc == d2) {
                    t.e[n].dr = (signed char)dr;
                    t.e[n].dc = (signed char)dc;
                    t.e[n].gc = 0; t.e[n].sv = 0.0f;
                    ++n;
                }
        if (n > start) { t.e[n-1].gc = (short)d2; t.e[n-1].sv = (float)csqrt_((double)d2); }
    }
    return t;
}
__constant__ Tab TAB = make_tab();

__device__ volatile float g_part_sum[NBLK];
__device__ volatile float g_part_cnt[NBLK];
__device__ volatile int   g_part_fg[NBLK];
__device__ unsigned int   g_done = 0;

// combined(px) = dist to nearest opposite-valued pixel (s binary => one EDT
// term is always zero), clamped at 10. Bit-parallel: rows packed to 128-bit
// masks; per offset (dr,dc) the opposite mask for 32 pixels at once is
// (self ^ funnel-shifted neighbor row) & validity. Offsets walked in ascending
// d2 groups; found is seeded with ~y_true so only contributing pixels gate the
// early exit; unfound pixels contribute exactly the clamp value 10.
__global__ __launch_bounds__(NT, 2)
void edt_kernel(const float* __restrict__ yp, const float* __restrict__ yt,
                float* __restrict__ out)
{
    __shared__ unsigned sS[SROWS][SSTR];
    __shared__ unsigned sY[HH][4];
    __shared__ float wsum[NWARP], wcnt[NWARP];
    __shared__ int s_islast;
    __shared__ unsigned s_fgw[4];
    __shared__ int s_first[BB], s_last[BB];

    const int slice = blockIdx.x;
    const int t = threadIdx.x;
    const int lane = t & 31, wp = t >> 5;
    const float* yps = yp + (size_t)slice * HH * WW;
    const float* yts = yt + (size_t)slice * HH * WW;

    // zero all stored words (guard rows + guard cols)
    for (int i = t; i < SROWS * SSTR; i += NT) ((unsigned*)sS)[i] = 0u;
    __syncthreads();

    // pack phase: one warp-ballot per (row, word); coalesced 128B loads
    for (int task = wp; task < HH * 4; task += NWARP) {
        int r = task >> 2, w = task & 3;
        unsigned ms = __ballot_sync(0xffffffffu, yps[r * WW + w * 32 + lane] > 0.7f);
        unsigned my = __ballot_sync(0xffffffffu, yts[r * WW + w * 32 + lane] != 0.0f);
        if (lane == 0) { sS[GR + r][1 + w] = ms; sY[r][w] = my; }
    }
    __syncthreads();

    // main phase: thread <-> (row, word), 32 pixels per thread
    const int r = t >> 2, w = t & 3;
    const unsigned self = sS[GR + r][1 + w];
    const unsigned ytm  = sY[r][w];
    const unsigned* rowbase = &sS[GR + r][0];
    int fgflag = (self != 0u);
    unsigned found = ~ytm;          // non-y_true pixels are don't-care
    unsigned gor = 0u;
    float sum = 0.0f;

    #pragma unroll 1
    for (int i = 0; i < TABN; ++i) {
        Ent e = TAB.e[i];
        const unsigned* rw = rowbase + (int)e.dr * SSTR;
        unsigned sh, valid;
        int dc = e.dc;
        if (dc >= 0) {              // look right: (W[w] >> dc) | (W[w+1] << (32-dc))
            sh = __funnelshift_r(rw[1 + w], rw[2 + w], dc);
            valid = (w == 3) ? (0xffffffffu >> dc) : 0xffffffffu;
        } else {                    // look left: (W[w] << k) | (W[w-1] >> (32-k))
            int k = -dc;
            sh = __funnelshift_l(rw[w], rw[1 + w], k);
            valid = (w == 0) ? (0xffffffffu << k) : 0xffffffffu;
        }
        unsigned rv = ((unsigned)(r + e.dr) < (unsigned)HH) ? 0xffffffffu : 0u;
        gor |= (self ^ sh) & valid & rv;
        if (e.gc) {                 // group (one d2 value) complete
            unsigned nw = gor & ~found;
            if (nw) { sum += e.sv * (float)__popc(nw); found |= nw; }
            if (found == 0xffffffffu) break;
        }
    }
    sum += 10.0f * (float)__popc(~found);   // unfound => dist >= 10 => clamp
    float cntf = (float)__popc(ytm);
    int anyfg = __syncthreads_or(fgflag);

    // block reduction (16 warps)
    #pragma unroll
    for (int o = 16; o > 0; o >>= 1) {
        sum  += __shfl_down_sync(0xffffffffu, sum,  o);
        cntf += __shfl_down_sync(0xffffffffu, cntf, o);
    }
    if (lane == 0) { wsum[wp] = sum; wcnt[wp] = cntf; }
    __syncthreads();
    if (t == 0) {
        float s = 0.0f, c = 0.0f;
        #pragma unroll
        for (int i = 0; i < NWARP; i++) { s += wsum[i]; c += wcnt[i]; }
        g_part_sum[slice] = s;
        g_part_cnt[slice] = c;
        g_part_fg[slice]  = anyfg;
        __threadfence();
        unsigned old = atomicAdd(&g_done, 1u);
        s_islast = (old == NBLK - 1u);
        if (s_islast) g_done = 0;   // self-reset for graph replay
    }
    __syncthreads();
    if (!s_islast) return;

    // fused finalize (last block): per-batch fg slice range + masked sum
    __threadfence();
    int f = (t < NS) ? g_part_fg[t] : 0;
    unsigned bal = __ballot_sync(0xffffffffu, f != 0);
    if (t < NS && lane == 0) s_fgw[wp] = bal;      // wp < 4 for t < 128
    __syncthreads();
    if (t < BB) {
        unsigned long long m = (unsigned long long)s_fgw[2 * t] |
                               ((unsigned long long)s_fgw[2 * t + 1] << 32);
        s_first[t] = m ? (__ffsll((long long)m) - 1) : 0;   // argmax(all-false)=0
        s_last[t]  = m ? (63 - __clzll((long long)m)) : (DD - 1);
    }
    __syncthreads();
    float ms = 0.0f, mc = 0.0f;
    if (t < NS) {
        int b = t >> 6, d = t & (DD - 1);
        int in = (d >= s_first[b]) && (d <= s_last[b]);
        ms = in ? g_part_sum[t] : 0.0f;
        mc = g_part_cnt[t];
    }
    #pragma unroll
    for (int o = 16; o > 0; o >>= 1) {
        ms += __shfl_down_sync(0xffffffffu, ms, o);
        mc += __shfl_down_sync(0xffffffffu, mc, o);
    }
    if (lane == 0) { wsum[wp] = ms; wcnt[wp] = mc; }
    __syncthreads();
    if (t == 0) {
        float s = 0.0f, c = 0.0f;
        #pragma unroll
        for (int i = 0; i < NWARP; i++) { s += wsum[i]; c += wcnt[i]; }
        out[0] = s / c;
    }
}

extern "C" void kernel_launch(void* const* d_in, const int* in_sizes, int n_in,
                              void* d_out, int out_size)
{
    const float* yp = (const float*)d_in[0];
    const float* yt = (const float*)d_in[1];
    float* out = (float*)d_out;
    edt_kernel<<<NBLK, NT>>>(yp, yt, out);
}